// round 16
// baseline (speedup 1.0000x reference)
#include <cuda_runtime.h>
#include <math_constants.h>
#include <limits.h>

#define NPTS   8192
#define BATCH  4
#define KNN    4
#define QPB    224
#define THREADS 896                // 224 query-groups x 4 lanes
#define GRPX   37                  // 37*4 = 148 blocks = 1 full wave

#define NBINS  512
#define XMIN   (-6.0f)
#define INVW   (NBINS / 12.0f)
#define SLACK  1e-3f               // >> all fp32 rounding at these magnitudes
#define SEED   256                 // phase-1 half-window (512 ranks total)
#define GUARD  256                 // sentinels each side (= SEED)

#define PTS_BYTES  ((NPTS + 2 * GUARD) * 16)    // 139264
#define IDXG_BYTES ((NPTS + 2 * GUARD) * 4)     // 34816
#define RANK_BYTES (NPTS * 4)                   // 32768
#define SMEM_BYTES (PTS_BYTES + IDXG_BYTES + RANK_BYTES + NBINS * 4 * 2)  // 210944

#define FULL 0xFFFFFFFFu

__device__ __forceinline__ int bin_of(float px) {
    int bin = (int)__fmul_rn(__fsub_rn(px, XMIN), INVW);
    return min(max(bin, 0), NBINS - 1);
}

__device__ __forceinline__ bool better(float s, int oj, float v, int iv) {
    return (s > v) | ((s == v) & (oj < iv));
}

__global__ __launch_bounds__(THREADS, 1)
void knn_sorted_kernel(const float* __restrict__ x, float* __restrict__ out) {
    extern __shared__ char smem_raw[];
    float4* __restrict__ pts_s   = (float4*)smem_raw + GUARD;                 // [-GUARD, NPTS+GUARD)
    int*    __restrict__ idx_g   = (int*)(smem_raw + PTS_BYTES) + GUARD;      // guarded orig-idx
    int*    __restrict__ rank_of = (int*)(smem_raw + PTS_BYTES + IDXG_BYTES);
    int*    __restrict__ cnt     = (int*)(smem_raw + PTS_BYTES + IDXG_BYTES + RANK_BYTES);
    int*    __restrict__ tmp     = cnt + NBINS;

    const int b = blockIdx.y;
    const float* __restrict__ xb = x + (size_t)b * NPTS * 3;
    const int tid = threadIdx.x;

    // ---- 0) sentinels: s evaluates to -inf, oj = INT_MAX -> never selected
    if (tid < 2 * GUARD) {
        const int pos = (tid < GUARD) ? (tid - GUARD) : (NPTS + tid - GUARD);
        const float gx = (tid < GUARD) ? -1e30f : 1e30f;
        pts_s[pos] = make_float4(gx, 0.0f, 0.0f, -CUDART_INF_F);
        idx_g[pos] = INT_MAX;
    }

    // ---- 1) histogram over x-bins
    for (int i = tid; i < NBINS; i += THREADS) cnt[i] = 0;
    __syncthreads();
    for (int j = tid; j < NPTS; j += THREADS)
        atomicAdd(&cnt[bin_of(xb[3 * j])], 1);
    __syncthreads();

    // ---- 2) exclusive prefix (Kogge-Stone)
    if (tid < NBINS) tmp[tid] = cnt[tid];
    __syncthreads();
    for (int d = 1; d < NBINS; d <<= 1) {
        int v = 0;
        if (tid < NBINS && tid >= d) v = tmp[tid - d];
        __syncthreads();
        if (tid < NBINS) tmp[tid] += v;
        __syncthreads();
    }
    if (tid < NBINS) cnt[tid] = tmp[tid] - cnt[tid];   // start offsets (cursor)
    __syncthreads();

    // ---- 3) scatter; record ranks. After this, cnt[k] = END offset of bin k.
    for (int j = tid; j < NPTS; j += THREADS) {
        float px = xb[3 * j + 0];
        float py = xb[3 * j + 1];
        float pz = xb[3 * j + 2];
        int pos = atomicAdd(&cnt[bin_of(px)], 1);
        pts_s[pos] = make_float4(px, py, pz, -0.5f * (px * px + py * py + pz * pz));
        idx_g[pos] = j;
        rank_of[j] = pos;
    }
    __syncthreads();

    // ---- 4) one query per 4-lane group, lane-local top-4 streaming
    const int qi = tid >> 2, sl = tid & 3;
    const int q  = blockIdx.x * QPB + qi;
    const bool active = (q < NPTS);
    const int qc = active ? q : (NPTS - 1);            // inactive groups compute harmlessly

    const int r = rank_of[qc];
    const float4 qp = pts_s[r];
    const float qx = qp.x, qy = qp.y, qz = qp.z;
    const float qh2 = -2.0f * qp.w;                    // ||q||^2

    float v0 = -CUDART_INF_F, v1 = -CUDART_INF_F, v2 = -CUDART_INF_F, v3 = -CUDART_INF_F;
    int   o0 = INT_MAX, o1 = INT_MAX, o2 = INT_MAX, o3 = INT_MAX;

#define EVAL_INSERT(POS)                                                       \
    do {                                                                       \
        const float4 p = pts_s[POS];                                           \
        float s = __fmaf_rn(qx, p.x, p.w);                                     \
        s = __fmaf_rn(qy, p.y, s);                                             \
        s = __fmaf_rn(qz, p.z, s);                                             \
        if (s >= v3) {                                                         \
            const int oj = idx_g[POS];                                         \
            if (better(s, oj, v3, o3)) {                                       \
                if (better(s, oj, v2, o2)) {                                   \
                    v3 = v2; o3 = o2;                                          \
                    if (better(s, oj, v1, o1)) {                               \
                        v2 = v1; o2 = o1;                                      \
                        if (better(s, oj, v0, o0)) {                           \
                            v1 = v0; o1 = o0; v0 = s; o0 = oj;                 \
                        } else { v1 = s; o1 = oj; }                            \
                    } else { v2 = s; o2 = oj; }                                \
                } else { v3 = s; o3 = oj; }                                    \
            }                                                                  \
        }                                                                      \
    } while (0)

    // ---- 4a) phase 1: fixed 512-rank window [r-SEED, r+SEED), stride 4, no votes
    {
        int pos = r - SEED + sl;
        #pragma unroll 4
        for (int k = 0; k < (2 * SEED) / 4; ++k) {
            EVAL_INSERT(pos);
            pos += 4;
        }
    }

    // ---- 4b) merge1 (width-4 shfl): exact 4th-best of the group union
    float v3a;
    {
        int ptr = 0;
        #pragma unroll
        for (int k = 0; k < KNN; ++k) {
            float cs  = (ptr == 0) ? v0 : (ptr == 1) ? v1 : (ptr == 2) ? v2 : v3;
            int   coj = (ptr == 0) ? o0 : (ptr == 1) ? o1 : (ptr == 2) ? o2 : o3;
            #pragma unroll
            for (int d = 1; d < 4; d <<= 1) {
                const float os  = __shfl_xor_sync(FULL, cs, d, 4);
                const int   ooj = __shfl_xor_sync(FULL, coj, d, 4);
                if (better(os, ooj, cs, coj)) { cs = os; coj = ooj; }
            }
            v3a = cs;                                   // after k=3: union 4th-best
            const int myoj = (ptr == 0) ? o0 : (ptr == 1) ? o1 : (ptr == 2) ? o2 : o3;
            if (myoj == coj) ptr++;                     // ojs unique -> one lane advances
        }
    }

    // ---- 4c) exact remaining range from bins (sound: monotone bin_of + slack)
    const float xlim = __fsqrt_ru(qh2 - 2.0f * v3a + SLACK);
    const int sbin = bin_of(__fsub_rd(qx, xlim));
    const int ebin = bin_of(__fadd_ru(qx, xlim));
    const int startR = (sbin > 0) ? cnt[sbin - 1] : 0;  // cnt = end offsets
    const int stopR  = cnt[ebin];

    // ---- 4d) phase 2: disjoint remainder, vote-free streaming
    {
        int pos = startR + sl;
        const int lim = r - SEED;
        while (pos < lim) { EVAL_INSERT(pos); pos += 4; }
    }
    {
        int pos = r + SEED + sl;
        while (pos < stopR) { EVAL_INSERT(pos); pos += 4; }
    }
#undef EVAL_INSERT

    // ---- 4e) final merge; lane sl keeps result slot sl
    int res_oj = 0;
    {
        int ptr = 0;
        #pragma unroll
        for (int k = 0; k < KNN; ++k) {
            float cs  = (ptr == 0) ? v0 : (ptr == 1) ? v1 : (ptr == 2) ? v2 : v3;
            int   coj = (ptr == 0) ? o0 : (ptr == 1) ? o1 : (ptr == 2) ? o2 : o3;
            #pragma unroll
            for (int d = 1; d < 4; d <<= 1) {
                const float os  = __shfl_xor_sync(FULL, cs, d, 4);
                const int   ooj = __shfl_xor_sync(FULL, coj, d, 4);
                if (better(os, ooj, cs, coj)) { cs = os; coj = ooj; }
            }
            if (k == sl) res_oj = coj;
            const int myoj = (ptr == 0) ? o0 : (ptr == 1) ? o1 : (ptr == 2) ? o2 : o3;
            if (myoj == coj) ptr++;
        }
    }

    // ---- 5) lane sl writes neighbor sl of query q
    if (active) {
        const float4 nb = pts_s[rank_of[res_oj]];
        float* __restrict__ o = out + (((size_t)b * NPTS + q) * KNN + sl) * 3;
        o[0] = nb.x; o[1] = nb.y; o[2] = nb.z;
    }
}

extern "C" void kernel_launch(void* const* d_in, const int* in_sizes, int n_in,
                              void* d_out, int out_size) {
    (void)n_in; (void)in_sizes; (void)out_size;
    const float* x = (const float*)d_in[0];
    float* out = (float*)d_out;

    cudaFuncSetAttribute(knn_sorted_kernel,
                         cudaFuncAttributeMaxDynamicSharedMemorySize, SMEM_BYTES);

    dim3 grid(GRPX, BATCH, 1);   // 148 blocks = 1 full wave
    dim3 block(THREADS, 1, 1);
    knn_sorted_kernel<<<grid, block, SMEM_BYTES>>>(x, out);
}

// round 17
// speedup vs baseline: 1.4227x; 1.4227x over previous
#include <cuda_runtime.h>
#include <math_constants.h>
#include <limits.h>

#define NPTS   8192
#define BATCH  4
#define KNN    4
#define QPB    224
#define THREADS 896                // 224 query-groups x 4 lanes
#define GRPX   37                  // 37*4 = 148 blocks = 1 full wave

#define NBINS  512
#define XMIN   (-6.0f)
#define INVW   (NBINS / 12.0f)
#define SLACK  1e-3f               // >> all fp32 rounding at these magnitudes
#define SEED   256                 // phase-1 half-window (512 ranks total)
#define GUARD  272                 // sentinels each side (covers SEED + overshoot 16)

#define PTS_BYTES  ((NPTS + 2 * GUARD) * 16)
#define IDXG_BYTES ((NPTS + 2 * GUARD) * 4)
#define RANK_BYTES (NPTS * 4)
#define SMEM_BYTES (PTS_BYTES + IDXG_BYTES + RANK_BYTES + NBINS * 4 * 2)

#define FULL 0xFFFFFFFFu

__device__ __forceinline__ int bin_of(float px) {
    int bin = (int)__fmul_rn(__fsub_rn(px, XMIN), INVW);
    return min(max(bin, 0), NBINS - 1);
}

__device__ __forceinline__ bool better(float s, int oj, float v, int iv) {
    return (s > v) | ((s == v) & (oj < iv));
}

__global__ __launch_bounds__(THREADS, 1)
void knn_sorted_kernel(const float* __restrict__ x, float* __restrict__ out) {
    extern __shared__ char smem_raw[];
    float4* __restrict__ pts_s   = (float4*)smem_raw + GUARD;              // [-GUARD, NPTS+GUARD)
    int*    __restrict__ idx_g   = (int*)(smem_raw + PTS_BYTES) + GUARD;
    int*    __restrict__ rank_of = (int*)(smem_raw + PTS_BYTES + IDXG_BYTES);
    int*    __restrict__ cnt     = (int*)(smem_raw + PTS_BYTES + IDXG_BYTES + RANK_BYTES);
    int*    __restrict__ tmp     = cnt + NBINS;

    const int b = blockIdx.y;
    const float* __restrict__ xb = x + (size_t)b * NPTS * 3;
    const int tid = threadIdx.x;

    // ---- 0) sentinels: s -> -inf (never selected)
    for (int i = tid; i < 2 * GUARD; i += THREADS) {
        const int pos = (i < GUARD) ? (i - GUARD) : (NPTS + i - GUARD);
        const float gx = (i < GUARD) ? -1e30f : 1e30f;
        pts_s[pos] = make_float4(gx, 0.0f, 0.0f, -CUDART_INF_F);
        idx_g[pos] = INT_MAX;
    }

    // ---- 1) histogram over x-bins
    for (int i = tid; i < NBINS; i += THREADS) cnt[i] = 0;
    __syncthreads();
    for (int j = tid; j < NPTS; j += THREADS)
        atomicAdd(&cnt[bin_of(xb[3 * j])], 1);
    __syncthreads();

    // ---- 2) exclusive prefix (Kogge-Stone)
    if (tid < NBINS) tmp[tid] = cnt[tid];
    __syncthreads();
    for (int d = 1; d < NBINS; d <<= 1) {
        int v = 0;
        if (tid < NBINS && tid >= d) v = tmp[tid - d];
        __syncthreads();
        if (tid < NBINS) tmp[tid] += v;
        __syncthreads();
    }
    if (tid < NBINS) cnt[tid] = tmp[tid] - cnt[tid];
    __syncthreads();

    // ---- 3) scatter; record ranks. After this, cnt[k] = END offset of bin k.
    for (int j = tid; j < NPTS; j += THREADS) {
        float px = xb[3 * j + 0];
        float py = xb[3 * j + 1];
        float pz = xb[3 * j + 2];
        int pos = atomicAdd(&cnt[bin_of(px)], 1);
        pts_s[pos] = make_float4(px, py, pz, -0.5f * (px * px + py * py + pz * pz));
        idx_g[pos] = j;
        rank_of[j] = pos;
    }
    __syncthreads();

    // ---- 4) one query per 4-lane group; lane-local top-4; branch-filtered stream
    const int qi = tid >> 2, sl = tid & 3;
    const int q  = blockIdx.x * QPB + qi;
    const bool active = (q < NPTS);
    const int qc = active ? q : (NPTS - 1);

    const int r = rank_of[qc];
    const float4 qp = pts_s[r];
    const float qx = qp.x, qy = qp.y, qz = qp.z;
    const float qh2 = -2.0f * qp.w;

    float v0 = -CUDART_INF_F, v1 = -CUDART_INF_F, v2 = -CUDART_INF_F, v3 = -CUDART_INF_F;
    int   o0 = INT_MAX, o1 = INT_MAX, o2 = INT_MAX, o3 = INT_MAX;

    // single-candidate exact insert (used on rare filter hits + remainders)
#define INS1(S, POS)                                                           \
    do {                                                                       \
        if ((S) >= v3) {                                                       \
            const int oj_ = idx_g[POS];                                        \
            if (better((S), oj_, v3, o3)) {                                    \
                if (better((S), oj_, v2, o2)) {                                \
                    v3 = v2; o3 = o2;                                          \
                    if (better((S), oj_, v1, o1)) {                            \
                        v2 = v1; o2 = o1;                                      \
                        if (better((S), oj_, v0, o0)) {                        \
                            v1 = v0; o1 = o0; v0 = (S); o0 = oj_;              \
                        } else { v1 = (S); o1 = oj_; }                         \
                    } else { v2 = (S); o2 = oj_; }                             \
                } else { v3 = (S); o3 = oj_; }                                 \
            }                                                                  \
        }                                                                      \
    } while (0)

    // 4-candidate filtered step at pos, pos+4, pos+8, pos+12 (one rare branch)
#define STEP4(POS)                                                             \
    do {                                                                       \
        const float4 pa = pts_s[(POS)];                                        \
        const float4 pb = pts_s[(POS) + 4];                                    \
        const float4 pc = pts_s[(POS) + 8];                                    \
        const float4 pd = pts_s[(POS) + 12];                                   \
        float sa = __fmaf_rn(qx, pa.x, pa.w);                                  \
        sa = __fmaf_rn(qy, pa.y, sa); sa = __fmaf_rn(qz, pa.z, sa);            \
        float sb = __fmaf_rn(qx, pb.x, pb.w);                                  \
        sb = __fmaf_rn(qy, pb.y, sb); sb = __fmaf_rn(qz, pb.z, sb);            \
        float sc = __fmaf_rn(qx, pc.x, pc.w);                                  \
        sc = __fmaf_rn(qy, pc.y, sc); sc = __fmaf_rn(qz, pc.z, sc);            \
        float sd = __fmaf_rn(qx, pd.x, pd.w);                                  \
        sd = __fmaf_rn(qy, pd.y, sd); sd = __fmaf_rn(qz, pd.z, sd);            \
        const float m = fmaxf(fmaxf(sa, sb), fmaxf(sc, sd));                   \
        if (m >= v3) {                                                         \
            INS1(sa, (POS));                                                   \
            INS1(sb, (POS) + 4);                                               \
            INS1(sc, (POS) + 8);                                               \
            INS1(sd, (POS) + 12);                                              \
        }                                                                      \
    } while (0)

    // ---- 4a) phase 1: fixed window [r-SEED, r+SEED), 16 ranks per lane-iter
    {
        int pos = r - SEED + sl;
        #pragma unroll 2
        for (int k = 0; k < (2 * SEED) / 16; ++k) {   // 32 filtered steps
            STEP4(pos);
            pos += 16;
        }
    }

    // ---- 4b) merge1 (width-4 shfl): exact 4th-best of group union
    float v3a;
    {
        int ptr = 0;
        #pragma unroll
        for (int k = 0; k < KNN; ++k) {
            float cs  = (ptr == 0) ? v0 : (ptr == 1) ? v1 : (ptr == 2) ? v2 : v3;
            int   coj = (ptr == 0) ? o0 : (ptr == 1) ? o1 : (ptr == 2) ? o2 : o3;
            #pragma unroll
            for (int d = 1; d < 4; d <<= 1) {
                const float os  = __shfl_xor_sync(FULL, cs, d, 4);
                const int   ooj = __shfl_xor_sync(FULL, coj, d, 4);
                if (better(os, ooj, cs, coj)) { cs = os; coj = ooj; }
            }
            v3a = cs;
            const int myoj = (ptr == 0) ? o0 : (ptr == 1) ? o1 : (ptr == 2) ? o2 : o3;
            if (myoj == coj) ptr++;
        }
    }

    // ---- 4c) exact remaining rank range from bins (sound via monotone bin_of)
    const float xlim = __fsqrt_ru(qh2 - 2.0f * v3a + SLACK);
    const int sbin = bin_of(__fsub_rd(qx, xlim));
    const int ebin = bin_of(__fadd_ru(qx, xlim));
    const int startR = (sbin > 0) ? cnt[sbin - 1] : 0;
    const int stopR  = cnt[ebin];

    // ---- 4d) phase 2 left: [startR, r-SEED) — full groups, then guarded tail
    {
        const int lim = r - SEED;
        int base = startR;
        for (; base + 16 <= lim; base += 16) {
            STEP4(base + sl);
        }
        // remainder (<16 ranks): guard against re-entering the seed window
        for (int pos = base + sl; pos < lim; pos += 4) {
            const float4 p = pts_s[pos];
            float s = __fmaf_rn(qx, p.x, p.w);
            s = __fmaf_rn(qy, p.y, s);
            s = __fmaf_rn(qz, p.z, s);
            INS1(s, pos);
        }
    }
    // ---- 4e) phase 2 right: [r+SEED, stopR) — overshoot past stopR is provably
    //          harmless (s < v3a - SLACK/2 <= v3_final), guards cover smem range.
    {
        for (int pos = r + SEED + sl; pos < stopR; pos += 16) {
            STEP4(pos);
        }
    }
#undef STEP4
#undef INS1

    // ---- 4f) final merge; lane sl keeps result slot sl
    int res_oj = 0;
    {
        int ptr = 0;
        #pragma unroll
        for (int k = 0; k < KNN; ++k) {
            float cs  = (ptr == 0) ? v0 : (ptr == 1) ? v1 : (ptr == 2) ? v2 : v3;
            int   coj = (ptr == 0) ? o0 : (ptr == 1) ? o1 : (ptr == 2) ? o2 : o3;
            #pragma unroll
            for (int d = 1; d < 4; d <<= 1) {
                const float os  = __shfl_xor_sync(FULL, cs, d, 4);
                const int   ooj = __shfl_xor_sync(FULL, coj, d, 4);
                if (better(os, ooj, cs, coj)) { cs = os; coj = ooj; }
            }
            if (k == sl) res_oj = coj;
            const int myoj = (ptr == 0) ? o0 : (ptr == 1) ? o1 : (ptr == 2) ? o2 : o3;
            if (myoj == coj) ptr++;
        }
    }

    // ---- 5) lane sl writes neighbor sl of query q
    if (active) {
        const float4 nb = pts_s[rank_of[res_oj]];
        float* __restrict__ o = out + (((size_t)b * NPTS + q) * KNN + sl) * 3;
        o[0] = nb.x; o[1] = nb.y; o[2] = nb.z;
    }
}

extern "C" void kernel_launch(void* const* d_in, const int* in_sizes, int n_in,
                              void* d_out, int out_size) {
    (void)n_in; (void)in_sizes; (void)out_size;
    const float* x = (const float*)d_in[0];
    float* out = (float*)d_out;

    cudaFuncSetAttribute(knn_sorted_kernel,
                         cudaFuncAttributeMaxDynamicSharedMemorySize, SMEM_BYTES);

    dim3 grid(GRPX, BATCH, 1);   // 148 blocks = 1 full wave
    dim3 block(THREADS, 1, 1);
    knn_sorted_kernel<<<grid, block, SMEM_BYTES>>>(x, out);
}